// round 2
// baseline (speedup 1.0000x reference)
#include <cuda_runtime.h>
#include <math.h>

#define H 2048
#define W 2048
#define OH 2046
#define OW 2046
#define TILE 32
#define HALO 34
#define SROW 36           // padded shared row stride (floats)
#define GBX 64
#define GBY 64
#define NBLK (GBX * GBY)  // 4096

// Deterministic per-block partials; last block reduces them in fixed order.
__device__ double2 g_part[NBLK];
__device__ unsigned int g_count;   // zero at load; last block resets -> replay-safe

__global__ __launch_bounds__(256, 4)
void inverse_loss_fused(const float* __restrict__ predE,
                        const float* __restrict__ predV,
                        const float* __restrict__ strain,
                        float* __restrict__ out)
{
    __shared__ float sE [HALO * SROW];
    __shared__ float sXX[HALO * SROW];
    __shared__ float sYY[HALO * SROW];
    __shared__ float sXY[HALO * SROW];

    const int tid = threadIdx.y * 32 + threadIdx.x;
    const int oy0 = blockIdx.y * TILE;
    const int ox0 = blockIdx.x * TILE;

    // ---- load halo tile, compute stresses on the fly ----
    for (int idx = tid; idx < HALO * HALO; idx += 256) {
        const int y = idx / HALO;
        const int x = idx - y * HALO;
        const int gy = oy0 + y;
        const int gx = ox0 + x;
        float e = 0.f, sxx = 0.f, syy = 0.f, sxy = 0.f;
        if (gy < H && gx < W) {
            const int g = gy * W + gx;
            e = predE[g];
            const float vv  = predV[g];
            const float exx = strain[3 * g + 0];
            const float eyy = strain[3 * g + 1];
            const float exy = strain[3 * g + 2];
            const float frac = __fdividef(e, 1.0f - vv * vv);
            sxx = (exx + vv * eyy) * frac;
            syy = (vv * exx + eyy) * frac;
            sxy = exy * (1.0f - vv) * 0.5f * frac;
        }
        const int s = y * SROW + x;
        sE[s] = e; sXX[s] = sxx; sYY[s] = syy; sXY[s] = sxy;
    }
    __syncthreads();

    // ---- stencil: each thread = 1 column x 4 consecutive output rows ----
    const int lx     = threadIdx.x;
    const int lybase = threadIdx.y * 4;

    float rsE[6], rsXX[6], rsXY[6], dYY[6], dXY[6];
    #pragma unroll
    for (int r = 0; r < 6; r++) {
        const int base = (lybase + r) * SROW + lx;
        const float e0 = sE[base],  e1 = sE[base + 1],  e2 = sE[base + 2];
        rsE[r] = e0 + e1 + e2;
        const float a0 = sXX[base], a1 = sXX[base + 1], a2 = sXX[base + 2];
        rsXX[r] = a0 + a1 + a2;
        const float b0 = sYY[base],                     b2 = sYY[base + 2];
        dYY[r] = b0 - b2;
        const float c0 = sXY[base], c1 = sXY[base + 1], c2 = sXY[base + 2];
        dXY[r]  = c0 - c2;
        rsXY[r] = c0 + c1 + c2;
    }

    float lsum = 0.f;
    const int ox = ox0 + lx;
    #pragma unroll
    for (int k = 0; k < 4; k++) {
        const int oy = oy0 + lybase + k;
        if (oy < OH && ox < OW) {
            const float Ec = rsE[k] + rsE[k + 1] + rsE[k + 2];
            const float fx = (rsXX[k + 2] - rsXX[k]) + (dXY[k] + dXY[k + 1] + dXY[k + 2]);
            const float fy = (dYY[k] + dYY[k + 1] + dYY[k + 2]) + (rsXY[k + 2] - rsXY[k]);
            lsum += __fdividef(fabsf(fx) + fabsf(fy), Ec);
        }
    }

    // ---- E mean contribution: exact float4 partition, 4 elems/thread ----
    const int bid = blockIdx.y * gridDim.x + blockIdx.x;
    float esum;
    {
        const float4* E4 = reinterpret_cast<const float4*>(predE);
        const float4 q = E4[(size_t)bid * 256 + tid];   // 4096 blocks * 256 thr == N/4
        esum = (q.x + q.y) + (q.z + q.w);
    }

    // ---- block reduction (warp shuffle -> shared -> thread 0) ----
    #pragma unroll
    for (int o = 16; o > 0; o >>= 1) {
        lsum += __shfl_down_sync(0xffffffffu, lsum, o);
        esum += __shfl_down_sync(0xffffffffu, esum, o);
    }
    __shared__ float wl[8], we[8];
    __shared__ int   sIsLast;
    if ((tid & 31) == 0) { wl[tid >> 5] = lsum; we[tid >> 5] = esum; }
    __syncthreads();
    if (tid == 0) {
        double L = 0.0, Es = 0.0;
        #pragma unroll
        for (int i = 0; i < 8; i++) { L += (double)wl[i]; Es += (double)we[i]; }
        g_part[bid] = make_double2(L, Es);
        __threadfence();
        const unsigned prev = atomicAdd(&g_count, 1u);
        sIsLast = (prev == NBLK - 1u) ? 1 : 0;
    }
    __syncthreads();

    // ---- last block: deterministic final reduction over all partials ----
    if (sIsLast) {
        double L = 0.0, E = 0.0;
        for (int i = tid; i < NBLK; i += 256) {
            const double2 v = g_part[i];
            L += v.x; E += v.y;
        }
        __shared__ double sl[256], se[256];
        sl[tid] = L; se[tid] = E;
        __syncthreads();
        for (int s = 128; s > 0; s >>= 1) {
            if (tid < s) { sl[tid] += sl[tid + s]; se[tid] += se[tid + s]; }
            __syncthreads();
        }
        if (tid == 0) {
            const double M = (double)OH * (double)OW;
            const double meanE = se[0] / ((double)H * (double)W);
            out[0] = (float)(sl[0] / M + fabs(meanE - 1.0) / 100.0);
            g_count = 0;   // reset for next graph replay
        }
    }
}

extern "C" void kernel_launch(void* const* d_in, const int* in_sizes, int n_in,
                              void* d_out, int out_size)
{
    const float* predE  = (const float*)d_in[0];
    const float* predV  = (const float*)d_in[1];
    const float* strain = (const float*)d_in[2];
    float* out = (float*)d_out;

    dim3 block(32, 8);
    dim3 grid(GBX, GBY);
    inverse_loss_fused<<<grid, block>>>(predE, predV, strain, out);
}

// round 3
// speedup vs baseline: 1.2886x; 1.2886x over previous
#include <cuda_runtime.h>
#include <math.h>
#include <stdint.h>

#define H 2048
#define W 2048
#define OH 2046
#define OW 2046
#define TILE 32
#define HALO 34
#define PTS  (HALO * HALO)       // 1156
#define SPTS (HALO * HALO * 3)   // 3468
#define NT   4096                // 64x64 tiles
#define NB   592                 // 4 blocks/SM * 148 SMs

// Deterministic per-block partials; last block (atomic ticket) reduces in fixed order.
__device__ double2 g_part[NB];
__device__ unsigned int g_count;   // zero at load; last block resets -> replay-safe

__device__ __forceinline__ uint32_t s2u(const void* p) {
    return (uint32_t)__cvta_generic_to_shared(p);
}
__device__ __forceinline__ void cpa4(uint32_t dst, const float* src, int sz) {
    asm volatile("cp.async.ca.shared.global [%0], [%1], 4, %2;"
                 :: "r"(dst), "l"(src), "r"(sz));
}
#define CP_COMMIT() asm volatile("cp.async.commit_group;" ::: "memory")
#define CP_WAIT1()  asm volatile("cp.async.wait_group 1;" ::: "memory")

__global__ __launch_bounds__(256, 4)
void inverse_loss_pipe(const float* __restrict__ predE,
                       const float* __restrict__ predV,
                       const float* __restrict__ strain,
                       float* __restrict__ out)
{
    // Raw inputs, double-buffered (45.2 KB total). Stress recomputed at use.
    __shared__ float sE[2][PTS];
    __shared__ float sV[2][PTS];
    __shared__ float sS[2][SPTS];   // interleaved [p*3 + c] (stride-3 LDS: conflict-free)
    __shared__ float wl[8], we[8];
    __shared__ double swl[8], swe[8];
    __shared__ int sIsLast;

    const int tid    = threadIdx.x;
    const int lx     = tid & 31;
    const int lybase = (tid >> 5) * 4;

    // ---- prefetch one tile's raw inputs into stage st ----
    auto prefetch = [&](int t, int st) {
        const int oy0 = (t >> 6) * TILE;
        const int ox0 = (t & 63) * TILE;
        #pragma unroll
        for (int i = 0; i < 5; i++) {
            const int idx = tid + i * 256;
            if (idx < PTS) {
                const int y = idx / HALO, x = idx - y * HALO;
                const int gy = oy0 + y, gx = ox0 + x;
                const bool ok = (gy < H) && (gx < W);
                const int g = ok ? gy * W + gx : 0;
                const int sz = ok ? 4 : 0;
                cpa4(s2u(&sE[st][idx]), predE + g, sz);
                cpa4(s2u(&sV[st][idx]), predV + g, sz);
            }
        }
        #pragma unroll
        for (int i = 0; i < 14; i++) {
            const int j = tid + i * 256;
            if (j < SPTS) {
                const int p = j / 3, c = j - p * 3;
                const int y = p / HALO, x = p - y * HALO;
                const int gy = oy0 + y, gx = ox0 + x;
                const bool ok = (gy < H) && (gx < W);
                const int g = ok ? 3 * (gy * W + gx) + c : 0;
                cpa4(s2u(&sS[st][j]), strain + g, ok ? 4 : 0);
            }
        }
    };

    const int t0 = blockIdx.x;
    float lsum = 0.f, esum = 0.f;

    prefetch(t0, 0);
    CP_COMMIT();

    int k = 0;
    for (int t = t0; t < NT; t += NB, k++) {
        const int tn = t + NB;
        if (tn < NT) prefetch(tn, (k + 1) & 1);
        CP_COMMIT();
        CP_WAIT1();            // current tile's group complete (this thread)
        __syncthreads();       // ... and every thread's

        const int st = k & 1;
        const float* __restrict__ e_ = sE[st];
        const float* __restrict__ v_ = sV[st];
        const float* __restrict__ s_ = sS[st];

        // ---- E-mean: each tile owns its 32x32 interior (exact partition) ----
        #pragma unroll
        for (int i = 0; i < 5; i++) {
            const int idx = tid + i * 256;
            if (idx < PTS) {
                const int y = idx / HALO, x = idx - y * HALO;
                if (x < TILE && y < TILE) esum += e_[idx];
            }
        }

        // ---- stencil: 1 column x 4 output rows per thread, row sums/diffs ----
        float rsE[6], rsXX[6], rsXY[6], dYY[6], dXY[6];
        #pragma unroll
        for (int r = 0; r < 6; r++) {
            float a = 0.f, b = 0.f, c3 = 0.f, dy = 0.f, dx = 0.f;
            const int p0 = (lybase + r) * HALO + lx;
            #pragma unroll
            for (int c = 0; c < 3; c++) {
                const int p = p0 + c;
                const float e   = e_[p];
                const float v   = v_[p];
                const float exx = s_[3 * p];
                const float eyy = s_[3 * p + 1];
                const float exy = s_[3 * p + 2];
                const float frac = __fdividef(e, 1.0f - v * v);
                const float sxx = (exx + v * eyy) * frac;
                const float syy = (v * exx + eyy) * frac;
                const float sxy = exy * (1.0f - v) * 0.5f * frac;
                a  += e;
                b  += sxx;
                c3 += sxy;
                if (c == 0) { dy = syy;  dx = sxy; }
                if (c == 2) { dy -= syy; dx -= sxy; }
            }
            rsE[r] = a; rsXX[r] = b; rsXY[r] = c3; dYY[r] = dy; dXY[r] = dx;
        }

        const int oy0 = (t >> 6) * TILE;
        const int ox  = (t & 63) * TILE + lx;
        #pragma unroll
        for (int q = 0; q < 4; q++) {
            const int oy = oy0 + lybase + q;
            if (oy < OH && ox < OW) {
                const float Ec = rsE[q] + rsE[q + 1] + rsE[q + 2];
                const float fx = (rsXX[q + 2] - rsXX[q]) + (dXY[q] + dXY[q + 1] + dXY[q + 2]);
                const float fy = (dYY[q] + dYY[q + 1] + dYY[q + 2]) + (rsXY[q + 2] - rsXY[q]);
                lsum += __fdividef(fabsf(fx) + fabsf(fy), Ec);
            }
        }
        __syncthreads();   // stage reads done before next iteration overwrites it
    }

    // ---- block reduction ----
    #pragma unroll
    for (int o = 16; o > 0; o >>= 1) {
        lsum += __shfl_down_sync(0xffffffffu, lsum, o);
        esum += __shfl_down_sync(0xffffffffu, esum, o);
    }
    if ((tid & 31) == 0) { wl[tid >> 5] = lsum; we[tid >> 5] = esum; }
    __syncthreads();
    if (tid == 0) {
        double L = 0.0, Es = 0.0;
        #pragma unroll
        for (int i = 0; i < 8; i++) { L += (double)wl[i]; Es += (double)we[i]; }
        g_part[blockIdx.x] = make_double2(L, Es);
        __threadfence();
        const unsigned prev = atomicAdd(&g_count, 1u);
        sIsLast = (prev == NB - 1u) ? 1 : 0;
    }
    __syncthreads();

    // ---- last block: deterministic final reduction over 592 partials ----
    if (sIsLast) {
        double L = 0.0, E = 0.0;
        for (int i = tid; i < NB; i += 256) {
            const double2 v = g_part[i];
            L += v.x; E += v.y;
        }
        #pragma unroll
        for (int o = 16; o > 0; o >>= 1) {
            L += __shfl_down_sync(0xffffffffu, L, o);
            E += __shfl_down_sync(0xffffffffu, E, o);
        }
        if ((tid & 31) == 0) { swl[tid >> 5] = L; swe[tid >> 5] = E; }
        __syncthreads();
        if (tid == 0) {
            double Lt = 0.0, Et = 0.0;
            #pragma unroll
            for (int i = 0; i < 8; i++) { Lt += swl[i]; Et += swe[i]; }
            const double M = (double)OH * (double)OW;
            const double meanE = Et / ((double)H * (double)W);
            out[0] = (float)(Lt / M + fabs(meanE - 1.0) / 100.0);
            g_count = 0;   // reset for next graph replay
        }
    }
}

extern "C" void kernel_launch(void* const* d_in, const int* in_sizes, int n_in,
                              void* d_out, int out_size)
{
    const float* predE  = (const float*)d_in[0];
    const float* predV  = (const float*)d_in[1];
    const float* strain = (const float*)d_in[2];
    float* out = (float*)d_out;

    inverse_loss_pipe<<<NB, 256>>>(predE, predV, strain, out);
}

// round 4
// speedup vs baseline: 1.6021x; 1.2433x over previous
#include <cuda_runtime.h>
#include <math.h>
#include <stdint.h>

#define H 2048
#define W 2048
#define NPTS (H * W)             // 4194304
#define OH 2046
#define OW 2046
#define TILE 32
#define HALO 34
#define PTS  (HALO * HALO)       // 1156
#define SROW 36                  // E row stride in shared (floats), 16B-aligned rows
#define SSROW 104                // strain/stress row stride (34*3=102 -> 104), 16B-aligned
#define NT   4096                // 64x64 tiles
#define NB   592                 // 4 blocks/SM * 148 SMs

// Deterministic per-block partials; last block (atomic ticket) reduces in fixed order.
__device__ double2 g_part[NB];
__device__ unsigned int g_count;   // zero at load; last block resets -> replay-safe

__device__ __forceinline__ uint32_t s2u(const void* p) {
    return (uint32_t)__cvta_generic_to_shared(p);
}
__device__ __forceinline__ void cpa16(uint32_t dst, const float* src, int sz) {
    asm volatile("cp.async.cg.shared.global [%0], [%1], 16, %2;"
                 :: "r"(dst), "l"(src), "r"(sz));
}
#define CP_COMMIT() asm volatile("cp.async.commit_group;" ::: "memory")
#define CP_WAIT1()  asm volatile("cp.async.wait_group 1;" ::: "memory")

__global__ __launch_bounds__(256, 4)
void inverse_loss_pipe(const float* __restrict__ predE,
                       const float* __restrict__ predV,
                       const float* __restrict__ strain,
                       float* __restrict__ out)
{
    // Raw inputs, double-buffered. Stress overwrites strain in-place in phase 1.
    __shared__ float sE[2][HALO * SROW];    // 2 * 4896 B
    __shared__ float sV[2][HALO * SROW];    // 2 * 4896 B
    __shared__ float sS[2][HALO * SSROW];   // 2 * 14144 B   (total ~47.9 KB)
    __shared__ float wl[8], we[8];
    __shared__ double swl[8], swe[8];
    __shared__ int sIsLast;

    const int tid    = threadIdx.x;
    const int lx     = tid & 31;
    const int lybase = (tid >> 5) * 4;

    // ---- vectorized 16B prefetch of one tile's raw inputs into stage st ----
    auto prefetch = [&](int t, int st) {
        const int oy0 = (t >> 6) * TILE;
        const int ox0 = (t & 63) * TILE;
        // E and V: 34 rows x 9 float4 segs (covers cols 0..35; cols 34-35 junk, unused)
        #pragma unroll
        for (int i = 0; i < 2; i++) {
            const int idx = tid + i * 256;
            if (idx < 34 * 9) {
                const int y = idx / 9, c = idx - y * 9;
                const int gy = oy0 + y;
                const int g  = gy * W + ox0 + 4 * c;
                const bool ok = (gy < H) && (g <= NPTS - 4);
                const int sz = ok ? 16 : 0;
                const int so = y * SROW + 4 * c;
                cpa16(s2u(&sE[st][so]), predE + (ok ? g : 0), sz);
                cpa16(s2u(&sV[st][so]), predV + (ok ? g : 0), sz);
            }
        }
        // strain: 34 rows x 26 float4 segs (covers floats 0..103 of 102 needed)
        #pragma unroll
        for (int i = 0; i < 4; i++) {
            const int idx = tid + i * 256;
            if (idx < 34 * 26) {
                const int y = idx / 26, c = idx - y * 26;
                const int gy = oy0 + y;
                const int f  = 3 * (gy * W + ox0) + 4 * c;
                const bool ok = (gy < H) && (f <= 3 * NPTS - 4);
                cpa16(s2u(&sS[st][y * SSROW + 4 * c]), strain + (ok ? f : 0), ok ? 16 : 0);
            }
        }
    };

    const int t0 = blockIdx.x;
    float lsum = 0.f, esum = 0.f;

    prefetch(t0, 0);
    CP_COMMIT();

    int k = 0;
    for (int t = t0; t < NT; t += NB, k++) {
        const int tn = t + NB;
        if (tn < NT) prefetch(tn, (k + 1) & 1);
        CP_COMMIT();
        CP_WAIT1();            // current tile's group complete (this thread)
        __syncthreads();       // ... and every thread's

        const int st = k & 1;
        const float* __restrict__ e_ = sE[st];
        const float* __restrict__ v_ = sV[st];
        float* __restrict__ s_ = sS[st];

        // ---- phase 1: stress transform, each point computed exactly once,
        //      written back in place over strain; E-mean rides along ----
        #pragma unroll
        for (int i = 0; i < 5; i++) {
            const int p = tid + i * 256;
            if (p < PTS) {
                const int y = p / HALO, x = p - y * HALO;
                const float e = e_[y * SROW + x];
                const float v = v_[y * SROW + x];
                if (x < TILE && y < TILE) esum += e;   // exact interior partition
                const int si = y * SSROW + 3 * x;
                const float exx = s_[si], eyy = s_[si + 1], exy = s_[si + 2];
                const float frac = __fdividef(e, 1.0f - v * v);
                s_[si]     = (exx + v * eyy) * frac;
                s_[si + 1] = (v * exx + eyy) * frac;
                s_[si + 2] = exy * (1.0f - v) * 0.5f * frac;
            }
        }
        __syncthreads();

        // ---- phase 2: stencil, 1 column x 4 output rows per thread ----
        float rsE[6], rsXX[6], rsXY[6], dYY[6], dXY[6];
        #pragma unroll
        for (int r = 0; r < 6; r++) {
            const int eb = (lybase + r) * SROW + lx;
            rsE[r] = e_[eb] + e_[eb + 1] + e_[eb + 2];
            const int sb = (lybase + r) * SSROW + 3 * lx;
            const float xx0 = s_[sb],     yy0 = s_[sb + 1], xy0 = s_[sb + 2];
            const float xx1 = s_[sb + 3],                   xy1 = s_[sb + 5];
            const float xx2 = s_[sb + 6], yy2 = s_[sb + 7], xy2 = s_[sb + 8];
            rsXX[r] = xx0 + xx1 + xx2;
            rsXY[r] = xy0 + xy1 + xy2;
            dYY[r]  = yy0 - yy2;
            dXY[r]  = xy0 - xy2;
        }

        const int oy0 = (t >> 6) * TILE;
        const int ox  = (t & 63) * TILE + lx;
        #pragma unroll
        for (int q = 0; q < 4; q++) {
            const int oy = oy0 + lybase + q;
            if (oy < OH && ox < OW) {
                const float Ec = rsE[q] + rsE[q + 1] + rsE[q + 2];
                const float fx = (rsXX[q + 2] - rsXX[q]) + (dXY[q] + dXY[q + 1] + dXY[q + 2]);
                const float fy = (dYY[q] + dYY[q + 1] + dYY[q + 2]) + (rsXY[q + 2] - rsXY[q]);
                lsum += __fdividef(fabsf(fx) + fabsf(fy), Ec);
            }
        }
        __syncthreads();   // stage reads done before next iteration overwrites it
    }

    // ---- block reduction ----
    #pragma unroll
    for (int o = 16; o > 0; o >>= 1) {
        lsum += __shfl_down_sync(0xffffffffu, lsum, o);
        esum += __shfl_down_sync(0xffffffffu, esum, o);
    }
    if ((tid & 31) == 0) { wl[tid >> 5] = lsum; we[tid >> 5] = esum; }
    __syncthreads();
    if (tid == 0) {
        double L = 0.0, Es = 0.0;
        #pragma unroll
        for (int i = 0; i < 8; i++) { L += (double)wl[i]; Es += (double)we[i]; }
        g_part[blockIdx.x] = make_double2(L, Es);
        __threadfence();
        const unsigned prev = atomicAdd(&g_count, 1u);
        sIsLast = (prev == NB - 1u) ? 1 : 0;
    }
    __syncthreads();

    // ---- last block: deterministic final reduction over 592 partials ----
    if (sIsLast) {
        double L = 0.0, E = 0.0;
        for (int i = tid; i < NB; i += 256) {
            const double2 v = g_part[i];
            L += v.x; E += v.y;
        }
        #pragma unroll
        for (int o = 16; o > 0; o >>= 1) {
            L += __shfl_down_sync(0xffffffffu, L, o);
            E += __shfl_down_sync(0xffffffffu, E, o);
        }
        if ((tid & 31) == 0) { swl[tid >> 5] = L; swe[tid >> 5] = E; }
        __syncthreads();
        if (tid == 0) {
            double Lt = 0.0, Et = 0.0;
            #pragma unroll
            for (int i = 0; i < 8; i++) { Lt += swl[i]; Et += swe[i]; }
            const double M = (double)OH * (double)OW;
            const double meanE = Et / ((double)H * (double)W);
            out[0] = (float)(Lt / M + fabs(meanE - 1.0) / 100.0);
            g_count = 0;   // reset for next graph replay
        }
    }
}

extern "C" void kernel_launch(void* const* d_in, const int* in_sizes, int n_in,
                              void* d_out, int out_size)
{
    const float* predE  = (const float*)d_in[0];
    const float* predV  = (const float*)d_in[1];
    const float* strain = (const float*)d_in[2];
    float* out = (float*)d_out;

    inverse_loss_pipe<<<NB, 256>>>(predE, predV, strain, out);
}